// round 11
// baseline (speedup 1.0000x reference)
#include <cuda_runtime.h>
#include <cuda_bf16.h>
#include <math.h>
#include <float.h>
#include <stdint.h>

#define BD 256      // batch
#define DD 4096     // dim

// Scratch (allocation-free: device globals)
// M = W + W^T decomposed exactly: M = S1*2^-8 + S2*2^-15 + S3*2^-22 + eps(|eps|<=2^-23)
__device__ signed char g_S1[(size_t)DD * DD];
__device__ signed char g_S2[(size_t)DD * DD];
__device__ signed char g_S3[(size_t)DD * DD];
__device__ signed char g_X8[(size_t)BD * DD];
__device__ float       g_grad[(size_t)BD * DD];

// ===========================================================================
// helpers
// ===========================================================================
__device__ __forceinline__ uint32_t smem_u32(const void* p) {
    uint32_t a;
    asm("{ .reg .u64 t; cvta.to.shared.u64 t, %1; cvt.u32.u64 %0, t; }" : "=r"(a) : "l"(p));
    return a;
}
__device__ __forceinline__ void cp16(uint32_t s, const void* g) {
    asm volatile("cp.async.cg.shared.global [%0], [%1], 16;\n" :: "r"(s), "l"(g));
}
#define CP_COMMIT() asm volatile("cp.async.commit_group;\n" ::: "memory")
#define CP_WAIT1()  asm volatile("cp.async.wait_group 1;\n" ::: "memory")

__device__ __forceinline__ void ldmx4(uint32_t* r, uint32_t a) {
    asm volatile("ldmatrix.sync.aligned.m8n8.x4.shared.b16 {%0,%1,%2,%3}, [%4];\n"
                 : "=r"(r[0]), "=r"(r[1]), "=r"(r[2]), "=r"(r[3]) : "r"(a));
}
__device__ __forceinline__ void mma_s8(int* d, const uint32_t* a, uint32_t b0, uint32_t b1) {
    asm volatile(
        "mma.sync.aligned.m16n8k32.row.col.s32.s8.s8.s32 "
        "{%0,%1,%2,%3}, {%4,%5,%6,%7}, {%8,%9}, {%0,%1,%2,%3};\n"
        : "+r"(d[0]), "+r"(d[1]), "+r"(d[2]), "+r"(d[3])
        : "r"(a[0]), "r"(a[1]), "r"(a[2]), "r"(a[3]), "r"(b0), "r"(b1));
}
__device__ __forceinline__ uint32_t swz(uint32_t off) {   // SW128
    return off ^ ((off >> 3) & 0x70);
}

// ---------------------------------------------------------------------------
// Kernel 1: M = W + W^T -> 3 int8 fixed-point slabs (R9, verified correct)
// ---------------------------------------------------------------------------
__device__ __forceinline__ void quant3(float a, signed char* o1, signed char* o2, signed char* o3) {
    float s1 = rintf(a * 256.f);
    float r1 = a - s1 * 0x1p-8f;
    float s2 = rintf(r1 * 32768.f);
    float r2 = r1 - s2 * 0x1p-15f;
    float s3 = rintf(r2 * 4194304.f);
    *o1 = (signed char)(int)s1;
    *o2 = (signed char)(int)s2;
    *o3 = (signed char)(int)s3;
}

__global__ __launch_bounds__(256) void k_buildM(const float* __restrict__ W) {
    int bx = blockIdx.x, by = blockIdx.y;
    if (by > bx) return;
    __shared__ float t1[64][65];
    __shared__ float t2[64][65];
    int tid = threadIdx.x;
    int r1 = by * 64, c1 = bx * 64;
    bool diag = (bx == by);

    #pragma unroll
    for (int i = 0; i < 4; i++) {
        int chunk = tid + i * 256;
        int row = chunk >> 4;
        int c4  = (chunk & 15) * 4;
        float4 v1 = *(const float4*)&W[(size_t)(r1 + row) * DD + c1 + c4];
        t1[row][c4] = v1.x; t1[row][c4+1] = v1.y; t1[row][c4+2] = v1.z; t1[row][c4+3] = v1.w;
        if (!diag) {
            float4 v2 = *(const float4*)&W[(size_t)(c1 + row) * DD + r1 + c4];
            t2[row][c4] = v2.x; t2[row][c4+1] = v2.y; t2[row][c4+2] = v2.z; t2[row][c4+3] = v2.w;
        } else {
            t2[row][c4] = v1.x; t2[row][c4+1] = v1.y; t2[row][c4+2] = v1.z; t2[row][c4+3] = v1.w;
        }
    }
    __syncthreads();

    #pragma unroll
    for (int i = 0; i < 2; i++) {
        int u   = tid + i * 256;
        int row = u >> 3;
        int cg  = (u & 7) * 8;
        {
            __align__(8) signed char o1[8], o2[8], o3[8];
            #pragma unroll
            for (int e = 0; e < 8; e++) {
                float a = t1[row][cg + e] + t2[cg + e][row];
                quant3(a, &o1[e], &o2[e], &o3[e]);
            }
            size_t off = (size_t)(r1 + row) * DD + c1 + cg;
            *(uint2*)&g_S1[off] = *(uint2*)o1;
            *(uint2*)&g_S2[off] = *(uint2*)o2;
            *(uint2*)&g_S3[off] = *(uint2*)o3;
        }
        if (!diag) {
            __align__(8) signed char o1[8], o2[8], o3[8];
            #pragma unroll
            for (int e = 0; e < 8; e++) {
                float a = t2[row][cg + e] + t1[cg + e][row];
                quant3(a, &o1[e], &o2[e], &o3[e]);
            }
            size_t off = (size_t)(c1 + row) * DD + r1 + cg;
            *(uint2*)&g_S1[off] = *(uint2*)o1;
            *(uint2*)&g_S2[off] = *(uint2*)o2;
            *(uint2*)&g_S3[off] = *(uint2*)o3;
        }
    }
}

// ---------------------------------------------------------------------------
// Kernel 2: x -> s8 (R9, verified)
// ---------------------------------------------------------------------------
__global__ void k_convX(const float* __restrict__ x) {
    int i = (blockIdx.x * 256 + threadIdx.x) * 16;
    __align__(16) signed char v[16];
    #pragma unroll
    for (int g = 0; g < 4; g++) {
        float4 f = *(const float4*)&x[i + g * 4];
        v[g*4+0] = (signed char)(int)f.x;
        v[g*4+1] = (signed char)(int)f.y;
        v[g*4+2] = (signed char)(int)f.z;
        v[g*4+3] = (signed char)(int)f.w;
    }
    *(uint4*)&g_X8[i] = *(uint4*)v;
}

// ---------------------------------------------------------------------------
// Kernel 3: int8 GEMM, register-budgeted retry.
// CTA 128x32, BK=128, 256 threads (8 warps, 4m x 2n, warp tile 32x16).
// acc[3][2][2][4] = 48 regs. 3-stage cp.async (dist 2). Fragment mapping
// identical to the R9-verified code. Grid (128, 2).
// ---------------------------------------------------------------------------
#define TM 128
#define TN 32
#define BKI 128
#define NITI (DD / BKI)            // 32
#define TA (128 * 128)             // A tile: 16KB
#define TB (32 * 128)              // B slab tile: 4KB
#define STG_B (TA + 3 * TB)        // 28KB
#define GSMEM (3 * STG_B + 1024)

extern __shared__ char g_dynsm[];

__global__ __launch_bounds__(256) void k_gemm(const float* __restrict__ bias) {
    int tid  = threadIdx.x;
    int lane = tid & 31, w = tid >> 5;
    int m0 = blockIdx.y * TM;
    int n0 = blockIdx.x * TN;
    int wm = (w >> 1) * 32;        // 0,32,64,96
    int wn = (w & 1) * 16;         // 0,16

    uint32_t base = (smem_u32(g_dynsm) + 1023u) & ~1023u;

    int acc[3][2][2][4];
    #pragma unroll
    for (int s = 0; s < 3; s++)
        #pragma unroll
        for (int a = 0; a < 2; a++)
            #pragma unroll
            for (int b = 0; b < 2; b++)
                #pragma unroll
                for (int c = 0; c < 4; c++) acc[s][a][b][c] = 0;

    const signed char* gA  = g_X8 + (size_t)m0 * DD;
    const signed char* gB1 = g_S1 + (size_t)n0 * DD;
    const signed char* gB2 = g_S2 + (size_t)n0 * DD;
    const signed char* gB3 = g_S3 + (size_t)n0 * DD;

    auto load_stage = [&](int s, int it) {
        int k0 = it * BKI;
        uint32_t sb = base + s * STG_B;
        // A: 1024 16B-chunks (128 rows x 8)
        #pragma unroll
        for (int i = 0; i < 4; i++) {
            int id  = tid + i * 256;
            int row = id >> 3;
            int cb  = (id & 7) * 16;
            uint32_t d = swz((uint32_t)(row * 128 + cb));
            cp16(sb + d, gA + (size_t)row * DD + k0 + cb);
        }
        // B slabs: 256 chunks each (32 rows x 8), 1 per thread per slab
        {
            int row = tid >> 3;
            int cb  = (tid & 7) * 16;
            uint32_t d = swz((uint32_t)(row * 128 + cb));
            cp16(sb + TA + d,            gB1 + (size_t)row * DD + k0 + cb);
            cp16(sb + TA + TB + d,       gB2 + (size_t)row * DD + k0 + cb);
            cp16(sb + TA + 2 * TB + d,   gB3 + (size_t)row * DD + k0 + cb);
        }
    };

    load_stage(0, 0); CP_COMMIT();
    load_stage(1, 1); CP_COMMIT();

    int lm   = lane & 15;
    int lh16 = (lane >> 4) * 16;
    int brow  = ((lane >> 4) & 1) * 8 + (lane & 7);
    int bbyte = ((lane >> 3) & 1) * 16;

    for (int it = 0; it < NITI; it++) {
        int s = it % 3;
        CP_WAIT1();
        __syncthreads();
        if (it + 2 < NITI) load_stage((it + 2) % 3, it + 2);
        CP_COMMIT();

        uint32_t sbA = base + s * STG_B;

        #pragma unroll
        for (int ks = 0; ks < 4; ks++) {
            int kb = ks * 32;
            uint32_t af[2][4];
            #pragma unroll
            for (int mt = 0; mt < 2; mt++)
                ldmx4(af[mt], sbA + swz((uint32_t)((wm + mt * 16 + lm) * 128 + kb + lh16)));
            #pragma unroll
            for (int sl = 0; sl < 3; sl++) {
                uint32_t sbB = sbA + TA + sl * TB;
                uint32_t bfr[4];
                ldmx4(bfr, sbB + swz((uint32_t)((wn + brow) * 128 + kb + bbyte)));
                #pragma unroll
                for (int mt = 0; mt < 2; mt++) {
                    mma_s8(acc[sl][mt][0], af[mt], bfr[0], bfr[1]);
                    mma_s8(acc[sl][mt][1], af[mt], bfr[2], bfr[3]);
                }
            }
        }
    }

    // epilogue: grad = acc1*2^-9 + acc2*2^-16 + acc3*2^-23 + bias (0.5 folded)
    int r = lane >> 2, c2 = (lane & 3) * 2;
    #pragma unroll
    for (int mt = 0; mt < 2; mt++)
        #pragma unroll
        for (int nf = 0; nf < 2; nf++) {
            int grow = m0 + wm + mt * 16 + r;
            int gcol = n0 + wn + nf * 8 + c2;
            float b0v = bias[gcol], b1v = bias[gcol + 1];
            #pragma unroll
            for (int e = 0; e < 4; e++) {
                float g = __int2float_rn(acc[0][mt][nf][e]) * 0x1p-9f
                        + __int2float_rn(acc[1][mt][nf][e]) * 0x1p-16f
                        + __int2float_rn(acc[2][mt][nf][e]) * 0x1p-23f
                        + ((e & 1) ? b1v : b0v);
                int rr = grow + (e >> 1) * 8;
                int cc = gcol + (e & 1);
                g_grad[(size_t)rr * DD + cc] = g;
            }
        }
}

// ---------------------------------------------------------------------------
// Kernel 4: per-row sampler (R7, verified ~18us)
// ---------------------------------------------------------------------------
#define ST 256
#define NW (ST / 32)

__global__ __launch_bounds__(ST) void k_sample(
    const float* __restrict__ x, const float* __restrict__ W,
    const int* __restrict__ radius_raw, const float* __restrict__ gum,
    const float* __restrict__ u, float* __restrict__ out)
{
    int row = blockIdx.x;
    int tid = threadIdx.x;
    int lane = tid & 31, wid = tid >> 5;

    __shared__ float s_wval[NW];
    __shared__ int   s_widx[NW];
    __shared__ float s_red[NW];
    __shared__ int   s_win;
    __shared__ int   s_idx[16];

    const float* xr  = x      + (size_t)row * DD;
    const float* gr  = g_grad + (size_t)row * DD;
    const float* gur = gum    + (size_t)row * DD;

    float4 vx[4], vg[4], vu[4];
    #pragma unroll
    for (int g = 0; g < 4; g++) vx[g] = *(const float4*)&xr[g * 1024 + tid * 4];
    #pragma unroll
    for (int g = 0; g < 4; g++) vg[g] = *(const float4*)&gr[g * 1024 + tid * 4];
    #pragma unroll
    for (int g = 0; g < 4; g++) vu[g] = *(const float4*)&gur[g * 1024 + tid * 4];

    float xv[16], scx[16], key[16];
    #pragma unroll
    for (int g = 0; g < 4; g++) {
        float fx[4] = {vx[g].x, vx[g].y, vx[g].z, vx[g].w};
        float fg[4] = {vg[g].x, vg[g].y, vg[g].z, vg[g].w};
        float fu[4] = {vu[g].x, vu[g].y, vu[g].z, vu[g].w};
        #pragma unroll
        for (int e = 0; e < 4; e++) {
            int k = g * 4 + e;
            xv[k]  = fx[e];
            scx[k] = (0.5f - fx[e]) * fg[e];
            float uu = fminf(fmaxf(fu[e], 1e-10f), 1.0f - 1e-10f);
            key[k] = scx[k] - __logf(-__logf(uu));
        }
    }

    // ---- lse_x ----
    float m = -FLT_MAX;
    #pragma unroll
    for (int k = 0; k < 16; k++) m = fmaxf(m, scx[k]);
    #pragma unroll
    for (int o = 16; o > 0; o >>= 1) m = fmaxf(m, __shfl_xor_sync(0xffffffffu, m, o));
    if (lane == 0) s_red[wid] = m;
    __syncthreads();
    float mx = s_red[0];
    #pragma unroll
    for (int ww = 1; ww < NW; ww++) mx = fmaxf(mx, s_red[ww]);
    __syncthreads();
    float s = 0.f;
    #pragma unroll
    for (int k = 0; k < 16; k++) s += __expf(scx[k] - mx);
    #pragma unroll
    for (int o = 16; o > 0; o >>= 1) s += __shfl_xor_sync(0xffffffffu, s, o);
    if (lane == 0) s_red[wid] = s;
    __syncthreads();
    float ss = 0.f;
    #pragma unroll
    for (int ww = 0; ww < NW; ww++) ss += s_red[ww];
    float lse_x = mx + logf(ss);

    // ---- initial per-warp candidate ----
    {
        float bv = -FLT_MAX; int bk = 0;
        #pragma unroll
        for (int k = 0; k < 16; k++)
            if (key[k] > bv) { bv = key[k]; bk = k; }
        int bj = (bk >> 2) * 1024 + tid * 4 + (bk & 3);
        #pragma unroll
        for (int o = 16; o > 0; o >>= 1) {
            float v2 = __shfl_down_sync(0xffffffffu, bv, o);
            int   i2 = __shfl_down_sync(0xffffffffu, bj, o);
            if (v2 > bv || (v2 == bv && i2 < bj)) { bv = v2; bj = i2; }
        }
        if (lane == 0) { s_wval[wid] = bv; s_widx[wid] = bj; }
    }
    __syncthreads();

    // ---- top-radius: winner-warp-only rescan ----
    int radius = radius_raw[row] + 1;
    for (int t = 0; t < radius; t++) {
        if (tid == 0) {
            float wv = s_wval[0]; int wj = s_widx[0]; int wwin = 0;
            #pragma unroll
            for (int ww = 1; ww < NW; ww++) {
                float v2 = s_wval[ww]; int i2 = s_widx[ww];
                if (v2 > wv || (v2 == wv && i2 < wj)) { wv = v2; wj = i2; wwin = ww; }
            }
            s_idx[t] = wj; s_win = wwin;
        }
        __syncthreads();
        if (wid == s_win && t + 1 < radius) {
            int j = s_idx[t];
            if (((j & 1023) >> 2) == tid) key[(j >> 10) * 4 + (j & 3)] = -FLT_MAX;
            float bv = -FLT_MAX; int bk = 0;
            #pragma unroll
            for (int k = 0; k < 16; k++)
                if (key[k] > bv) { bv = key[k]; bk = k; }
            int bj = (bk >> 2) * 1024 + tid * 4 + (bk & 3);
            #pragma unroll
            for (int o = 16; o > 0; o >>= 1) {
                float v2 = __shfl_down_sync(0xffffffffu, bv, o);
                int   i2 = __shfl_down_sync(0xffffffffu, bj, o);
                if (v2 > bv || (v2 == bv && i2 < bj)) { bv = v2; bj = i2; }
            }
            if (lane == 0) { s_wval[wid] = bv; s_widx[wid] = bj; }
        }
        __syncthreads();
    }

    unsigned mask = 0;
    for (int t = 0; t < radius; t++) {
        int j = s_idx[t];
        if (((j & 1023) >> 2) == tid) mask |= 1u << ((j >> 10) * 4 + (j & 3));
    }

    // ---- quad = 0.5 * d^T W d ----
    float q = 0.f;
    int rr = radius * radius;
    for (int p = tid; p < rr; p += ST) {
        int a = p / radius, bb = p - a * radius;
        int ia = s_idx[a], ib = s_idx[bb];
        float da = 1.f - 2.f * xr[ia];
        float db = 1.f - 2.f * xr[ib];
        q += da * db * W[(size_t)ia * DD + ib];
    }
    #pragma unroll
    for (int o = 16; o > 0; o >>= 1) q += __shfl_xor_sync(0xffffffffu, q, o);
    __syncthreads();
    if (lane == 0) s_red[wid] = q;
    __syncthreads();
    float quad = 0.f;
    #pragma unroll
    for (int ww = 0; ww < NW; ww++) quad += s_red[ww];
    quad *= 0.5f;
    __syncthreads();

    // ---- lse_y ----
    float m2 = -FLT_MAX;
    #pragma unroll
    for (int k = 0; k < 16; k++) {
        float v = (mask >> k) & 1 ? -scx[k] : scx[k];
        m2 = fmaxf(m2, v);
    }
    #pragma unroll
    for (int o = 16; o > 0; o >>= 1) m2 = fmaxf(m2, __shfl_xor_sync(0xffffffffu, m2, o));
    if (lane == 0) s_red[wid] = m2;
    __syncthreads();
    float mx2 = s_red[0];
    #pragma unroll
    for (int ww = 1; ww < NW; ww++) mx2 = fmaxf(mx2, s_red[ww]);
    __syncthreads();
    float s2 = 0.f;
    #pragma unroll
    for (int k = 0; k < 16; k++) {
        float v = (mask >> k) & 1 ? -scx[k] : scx[k];
        s2 += __expf(v - mx2);
    }
    #pragma unroll
    for (int o = 16; o > 0; o >>= 1) s2 += __shfl_xor_sync(0xffffffffu, s2, o);
    if (lane == 0) s_red[wid] = s2;
    __syncthreads();
    float ss2 = 0.f;
    #pragma unroll
    for (int ww = 0; ww < NW; ww++) ss2 += s_red[ww];
    float lse_y = mx2 + logf(ss2);

    // ---- accept + write ----
    float la = fminf(quad + lse_x - lse_y, 0.f);
    int accept = (__expf(la) > u[row]) ? 1 : 0;

    float* outr = out + (size_t)row * DD;
    #pragma unroll
    for (int g = 0; g < 4; g++) {
        int base = g * 1024 + tid * 4;
        float4 o4;
        float* po = (float*)&o4;
        #pragma unroll
        for (int e = 0; e < 4; e++) {
            int k = g * 4 + e;
            float yv = ((mask >> k) & 1) ? (1.f - xv[k]) : xv[k];
            po[e] = accept ? yv : xv[k];
        }
        *(float4*)&outr[base] = o4;
    }
}

// ---------------------------------------------------------------------------
extern "C" void kernel_launch(void* const* d_in, const int* in_sizes, int n_in,
                              void* d_out, int out_size) {
    const float* x          = (const float*)d_in[0];
    const float* W          = (const float*)d_in[1];
    const float* bias       = (const float*)d_in[2];
    const int*   radius_raw = (const int*)d_in[3];
    const float* gum        = (const float*)d_in[4];
    const float* u          = (const float*)d_in[5];
    float* out = (float*)d_out;

    cudaFuncSetAttribute(k_gemm, cudaFuncAttributeMaxDynamicSharedMemorySize, GSMEM);

    k_buildM<<<dim3(DD / 64, DD / 64), 256>>>(W);
    k_convX<<<(BD * DD) / 4096, 256>>>(x);
    k_gemm<<<dim3(DD / TN, BD / TM), 256, GSMEM>>>(bias);
    k_sample<<<BD, ST>>>(x, W, radius_raw, gum, u, out);
}

// round 12
// speedup vs baseline: 1.0455x; 1.0455x over previous
#include <cuda_runtime.h>
#include <cuda_bf16.h>
#include <math.h>
#include <float.h>
#include <stdint.h>

#define BD 256      // batch
#define DD 4096     // dim

// Scratch (allocation-free: device globals)
__device__ __nv_bfloat16 g_Xbf[(size_t)BD * DD];   // x in bf16 (exact: binary)
__device__ float         g_grad[(size_t)BD * DD];  // grad = 0.5(W+W^T)x + b

// ===========================================================================
// helpers
// ===========================================================================
__device__ __forceinline__ uint32_t smem_u32(const void* p) {
    uint32_t a;
    asm("{ .reg .u64 t; cvta.to.shared.u64 t, %1; cvt.u32.u64 %0, t; }" : "=r"(a) : "l"(p));
    return a;
}
__device__ __forceinline__ void cp16(uint32_t s, const void* g) {
    asm volatile("cp.async.cg.shared.global [%0], [%1], 16;\n" :: "r"(s), "l"(g));
}
#define CP_COMMIT() asm volatile("cp.async.commit_group;\n" ::: "memory")
#define CP_WAIT0()  asm volatile("cp.async.wait_group 0;\n" ::: "memory")
#define BAR_PROD()  asm volatile("bar.sync 1, 128;" ::: "memory")

__device__ __forceinline__ void ldmx4(uint32_t* r, uint32_t a) {
    asm volatile("ldmatrix.sync.aligned.m8n8.x4.shared.b16 {%0,%1,%2,%3}, [%4];\n"
                 : "=r"(r[0]), "=r"(r[1]), "=r"(r[2]), "=r"(r[3]) : "r"(a));
}
__device__ __forceinline__ void ldmx4t(uint32_t* r, uint32_t a) {
    asm volatile("ldmatrix.sync.aligned.m8n8.x4.trans.shared.b16 {%0,%1,%2,%3}, [%4];\n"
                 : "=r"(r[0]), "=r"(r[1]), "=r"(r[2]), "=r"(r[3]) : "r"(a));
}
__device__ __forceinline__ void mma16816(float* d, const uint32_t* a, uint32_t b0, uint32_t b1) {
    asm volatile(
        "mma.sync.aligned.m16n8k16.row.col.f32.bf16.bf16.f32 "
        "{%0,%1,%2,%3}, {%4,%5,%6,%7}, {%8,%9}, {%0,%1,%2,%3};\n"
        : "+f"(d[0]), "+f"(d[1]), "+f"(d[2]), "+f"(d[3])
        : "r"(a[0]), "r"(a[1]), "r"(a[2]), "r"(a[3]), "r"(b0), "r"(b1));
}
__device__ __forceinline__ uint32_t swz(uint32_t off) {   // SW128
    return off ^ ((off >> 3) & 0x70);
}

// ---------------------------------------------------------------------------
// Kernel 1: x -> bf16 (exact: x is 0/1)
// ---------------------------------------------------------------------------
__global__ void k_convX(const float* __restrict__ x) {
    int i = (blockIdx.x * 256 + threadIdx.x) * 4;
    float4 v = *(const float4*)&x[i];
    __nv_bfloat162 p0; p0.x = __float2bfloat16(v.x); p0.y = __float2bfloat16(v.y);
    __nv_bfloat162 p1; p1.x = __float2bfloat16(v.z); p1.y = __float2bfloat16(v.w);
    *(__nv_bfloat162*)&g_Xbf[i]     = p0;
    *(__nv_bfloat162*)&g_Xbf[i + 2] = p1;
}

// ---------------------------------------------------------------------------
// Kernel 2: FUSED symmetrize+split+GEMM.
//   grad = 0.5 * Xbf @ (bf16hi(W+W^T) + bf16lo(W+W^T)) + bias
// 256 threads: warps 0-3 = consumers (R7-verbatim MMA, warp tile 32x32,
// BM=BN=BK=64); warps 4-7 = producers (per iter: load fp32 tiles
// T1 = W[k0:+64][n0:+64] row-coalesced and T2 = W[n0:+64][k0:+64]
// row-coalesced, transpose T2 through padded smem, add, split to bf16 hi/lo,
// store swizzled [k][n]). Double-buffered; Grid (64, 4) = 256 CTAs.
// W fp32 re-reads are L2-resident (64MB < L2).
// ---------------------------------------------------------------------------
#define TM 64
#define TN 64
#define TKK 64
#define GNIT (DD / TKK)          // 64
#define SA_OFF 0                 // sA[2]  : 2 x 8KB bf16
#define SBH_OFF 16384            // sBh[2] : 2 x 8KB
#define SBL_OFF 32768            // sBl[2] : 2 x 8KB
#define ST2_OFF 49152            // sT2    : 64 x 65 fp32 = 16640B
#define GSMEM (49152 + 16640 + 256)

extern __shared__ char g_dynsm[];

__global__ void __launch_bounds__(256, 2) k_gemm_f(
    const float* __restrict__ W, const float* __restrict__ bias)
{
    int tid  = threadIdx.x;
    int lane = tid & 31, w = tid >> 5;
    int m0 = blockIdx.y * TM;
    int n0 = blockIdx.x * TN;

    uint32_t base = smem_u32(g_dynsm);
    float* sT2 = (float*)(g_dynsm + ST2_OFF);

    if (w >= 4) {
        // ================= PRODUCER =================
        int tid2 = tid - 128;
        int rr = tid2 >> 1;          // row 0..63
        int hf = tid2 & 1;           // column half
        const float* Wt1row = W + (size_t)rr * DD + n0 + hf * 32;       // T1: row k0+rr (k-offset added later)
        const float* Wt2row = W + (size_t)(n0 + rr) * DD + hf * 32;     // T2: row n0+rr, k-cols

        float4 t1r[8], t2r[8];
        // regs for it = 0 (k0 = 0)
        #pragma unroll
        for (int c = 0; c < 8; c++) {
            t1r[c] = *(const float4*)(Wt1row + (size_t)0 * DD + 0 + c * 4);      // W[rr][n0+hf*32+...] k0=0 row offset 0? see below
        }
        // NOTE: T1 row is W[k0+rr][...]: pointer = W + (k0+rr)*DD + n0+hf*32
        // Redefine cleanly:
        #pragma unroll
        for (int c = 0; c < 8; c++) {
            t1r[c] = *(const float4*)&W[(size_t)(0 + rr) * DD + n0 + hf * 32 + c * 4];
            t2r[c] = *(const float4*)&W[(size_t)(n0 + rr) * DD + 0 + hf * 32 + c * 4];
        }
        (void)Wt1row; (void)Wt2row;

        // ---- produce buffer `buf` for iteration `itp` using t1r/t2r ----
        auto produce = [&](int buf) {
            // stage T2 into padded fp32 smem: sT2[nn=rr][hf*32 + j]
            #pragma unroll
            for (int c = 0; c < 8; c++) {
                int j = hf * 32 + c * 4;
                sT2[rr * 65 + j    ] = t2r[c].x;
                sT2[rr * 65 + j + 1] = t2r[c].y;
                sT2[rr * 65 + j + 2] = t2r[c].z;
                sT2[rr * 65 + j + 3] = t2r[c].w;
            }
            BAR_PROD();
            // output row kk = rr, cols hf*32..+32 of M = T1 + T2^T
            const float* t1f = (const float*)t1r;
            #pragma unroll
            for (int g = 0; g < 4; g++) {
                __align__(16) __nv_bfloat16 h8[8], l8[8];
                #pragma unroll
                for (int e = 0; e < 8; e++) {
                    int c = g * 8 + e;
                    float v = t1f[c] + sT2[(hf * 32 + c) * 65 + rr];
                    __nv_bfloat16 h = __float2bfloat16(v);
                    h8[e] = h;
                    l8[e] = __float2bfloat16(v - __bfloat162float(h));
                }
                uint32_t d = swz((uint32_t)(rr * 128 + hf * 64 + g * 16));
                *(uint4*)(g_dynsm + SBH_OFF + buf * 8192 + d) = *(uint4*)h8;
                *(uint4*)(g_dynsm + SBL_OFF + buf * 8192 + d) = *(uint4*)l8;
            }
        };

        auto loadA = [&](int buf, int it) {
            int k0 = it * TKK;
            #pragma unroll
            for (int i = 0; i < 4; i++) {
                int id  = tid2 + i * 128;
                int row = id >> 3;
                int ce  = (id & 7) * 8;
                uint32_t d = swz((uint32_t)(row * 128 + ce * 2));
                cp16(base + SA_OFF + buf * 8192 + d,
                     g_Xbf + (size_t)(m0 + row) * DD + k0 + ce);
            }
        };

        auto loadRegs = [&](int it) {
            int k0 = it * TKK;
            #pragma unroll
            for (int c = 0; c < 8; c++) {
                t1r[c] = *(const float4*)&W[(size_t)(k0 + rr) * DD + n0 + hf * 32 + c * 4];
                t2r[c] = *(const float4*)&W[(size_t)(n0 + rr) * DD + k0 + hf * 32 + c * 4];
            }
        };

        // prologue: fill buffer 0 (it = 0)
        loadA(0, 0); CP_COMMIT();
        produce(0);
        loadRegs(1);
        CP_WAIT0();
        __syncthreads();           // buf0 ready

        for (int it = 0; it < GNIT; it++) {
            if (it + 1 < GNIT) {
                int nbuf = (it + 1) & 1;
                loadA(nbuf, it + 1); CP_COMMIT();
                produce(nbuf);
                if (it + 2 < GNIT) loadRegs(it + 2);
                CP_WAIT0();
            }
            __syncthreads();
        }
        // producers done (no epilogue)
    } else {
        // ================= CONSUMER (R7-verbatim MMA) =================
        int wm = (w >> 1) * 32;
        int wn = (w & 1) * 32;

        float acc[2][4][4];
        #pragma unroll
        for (int a = 0; a < 2; a++)
            #pragma unroll
            for (int b = 0; b < 4; b++)
                #pragma unroll
                for (int c = 0; c < 4; c++) acc[a][b][c] = 0.f;

        int lm = lane & 15, lh = (lane >> 4) * 8;

        __syncthreads();           // matches producer prologue sync

        for (int it = 0; it < GNIT; it++) {
            int buf = it & 1;
            uint32_t sbA = base + SA_OFF  + buf * 8192;
            uint32_t sbH = base + SBH_OFF + buf * 8192;
            uint32_t sbL = base + SBL_OFF + buf * 8192;

            #pragma unroll
            for (int ks = 0; ks < TKK; ks += 16) {
                uint32_t af[2][4], bh[2][4], bl[2][4];
                #pragma unroll
                for (int mt = 0; mt < 2; mt++) {
                    uint32_t byte = (uint32_t)((wm + mt * 16 + lm) * 128 + (ks + lh) * 2);
                    ldmx4(af[mt], sbA + swz(byte));
                }
                #pragma unroll
                for (int nb = 0; nb < 2; nb++) {
                    uint32_t byte = (uint32_t)((ks + lm) * 128 + (wn + nb * 16 + lh) * 2);
                    ldmx4t(bh[nb], sbH + swz(byte));
                    ldmx4t(bl[nb], sbL + swz(byte));
                }
                #pragma unroll
                for (int nt = 0; nt < 4; nt++) {
                    int nb = nt >> 1, sel = (nt & 1) * 2;
                    #pragma unroll
                    for (int mt = 0; mt < 2; mt++) {
                        mma16816(acc[mt][nt], af[mt], bh[nb][sel], bh[nb][sel + 1]);
                        mma16816(acc[mt][nt], af[mt], bl[nb][sel], bl[nb][sel + 1]);
                    }
                }
            }
            __syncthreads();
        }

        int r = lane >> 2, c2 = (lane & 3) * 2;
        #pragma unroll
        for (int mt = 0; mt < 2; mt++)
            #pragma unroll
            for (int nt = 0; nt < 4; nt++) {
                int grow = m0 + wm + mt * 16 + r;
                int gcol = n0 + wn + nt * 8 + c2;
                float b0v = bias[gcol], b1v = bias[gcol + 1];
                g_grad[(size_t)grow * DD + gcol]           = 0.5f * acc[mt][nt][0] + b0v;
                g_grad[(size_t)grow * DD + gcol + 1]       = 0.5f * acc[mt][nt][1] + b1v;
                g_grad[(size_t)(grow + 8) * DD + gcol]     = 0.5f * acc[mt][nt][2] + b0v;
                g_grad[(size_t)(grow + 8) * DD + gcol + 1] = 0.5f * acc[mt][nt][3] + b1v;
            }
    }
}

// ---------------------------------------------------------------------------
// Kernel 3: per-row sampler (R7, verified ~18us)
// ---------------------------------------------------------------------------
#define ST 256
#define NW (ST / 32)

__global__ __launch_bounds__(ST) void k_sample(
    const float* __restrict__ x, const float* __restrict__ W,
    const int* __restrict__ radius_raw, const float* __restrict__ gum,
    const float* __restrict__ u, float* __restrict__ out)
{
    int row = blockIdx.x;
    int tid = threadIdx.x;
    int lane = tid & 31, wid = tid >> 5;

    __shared__ float s_wval[NW];
    __shared__ int   s_widx[NW];
    __shared__ float s_red[NW];
    __shared__ int   s_win;
    __shared__ int   s_idx[16];

    const float* xr  = x      + (size_t)row * DD;
    const float* gr  = g_grad + (size_t)row * DD;
    const float* gur = gum    + (size_t)row * DD;

    float4 vx[4], vg[4], vu[4];
    #pragma unroll
    for (int g = 0; g < 4; g++) vx[g] = *(const float4*)&xr[g * 1024 + tid * 4];
    #pragma unroll
    for (int g = 0; g < 4; g++) vg[g] = *(const float4*)&gr[g * 1024 + tid * 4];
    #pragma unroll
    for (int g = 0; g < 4; g++) vu[g] = *(const float4*)&gur[g * 1024 + tid * 4];

    float xv[16], scx[16], key[16];
    #pragma unroll
    for (int g = 0; g < 4; g++) {
        float fx[4] = {vx[g].x, vx[g].y, vx[g].z, vx[g].w};
        float fg[4] = {vg[g].x, vg[g].y, vg[g].z, vg[g].w};
        float fu[4] = {vu[g].x, vu[g].y, vu[g].z, vu[g].w};
        #pragma unroll
        for (int e = 0; e < 4; e++) {
            int k = g * 4 + e;
            xv[k]  = fx[e];
            scx[k] = (0.5f - fx[e]) * fg[e];
            float uu = fminf(fmaxf(fu[e], 1e-10f), 1.0f - 1e-10f);
            key[k] = scx[k] - __logf(-__logf(uu));
        }
    }

    // ---- lse_x ----
    float m = -FLT_MAX;
    #pragma unroll
    for (int k = 0; k < 16; k++) m = fmaxf(m, scx[k]);
    #pragma unroll
    for (int o = 16; o > 0; o >>= 1) m = fmaxf(m, __shfl_xor_sync(0xffffffffu, m, o));
    if (lane == 0) s_red[wid] = m;
    __syncthreads();
    float mx = s_red[0];
    #pragma unroll
    for (int ww = 1; ww < NW; ww++) mx = fmaxf(mx, s_red[ww]);
    __syncthreads();
    float s = 0.f;
    #pragma unroll
    for (int k = 0; k < 16; k++) s += __expf(scx[k] - mx);
    #pragma unroll
    for (int o = 16; o > 0; o >>= 1) s += __shfl_xor_sync(0xffffffffu, s, o);
    if (lane == 0) s_red[wid] = s;
    __syncthreads();
    float ss = 0.f;
    #pragma unroll
    for (int ww = 0; ww < NW; ww++) ss += s_red[ww];
    float lse_x = mx + logf(ss);

    // ---- initial per-warp candidate ----
    {
        float bv = -FLT_MAX; int bk = 0;
        #pragma unroll
        for (int k = 0; k < 16; k++)
            if (key[k] > bv) { bv = key[k]; bk = k; }
        int bj = (bk >> 2) * 1024 + tid * 4 + (bk & 3);
        #pragma unroll
        for (int o = 16; o > 0; o >>= 1) {
            float v2 = __shfl_down_sync(0xffffffffu, bv, o);
            int   i2 = __shfl_down_sync(0xffffffffu, bj, o);
            if (v2 > bv || (v2 == bv && i2 < bj)) { bv = v2; bj = i2; }
        }
        if (lane == 0) { s_wval[wid] = bv; s_widx[wid] = bj; }
    }
    __syncthreads();

    // ---- top-radius: winner-warp-only rescan ----
    int radius = radius_raw[row] + 1;
    for (int t = 0; t < radius; t++) {
        if (tid == 0) {
            float wv = s_wval[0]; int wj = s_widx[0]; int wwin = 0;
            #pragma unroll
            for (int ww = 1; ww < NW; ww++) {
                float v2 = s_wval[ww]; int i2 = s_widx[ww];
                if (v2 > wv || (v2 == wv && i2 < wj)) { wv = v2; wj = i2; wwin = ww; }
            }
            s_idx[t] = wj; s_win = wwin;
        }
        __syncthreads();
        if (wid == s_win && t + 1 < radius) {
            int j = s_idx[t];
            if (((j & 1023) >> 2) == tid) key[(j >> 10) * 4 + (j & 3)] = -FLT_MAX;
            float bv = -FLT_MAX; int bk = 0;
            #pragma unroll
            for (int k = 0; k < 16; k++)
                if (key[k] > bv) { bv = key[k]; bk = k; }
            int bj = (bk >> 2) * 1024 + tid * 4 + (bk & 3);
            #pragma unroll
            for (int o = 16; o > 0; o >>= 1) {
                float v2 = __shfl_down_sync(0xffffffffu, bv, o);
                int   i2 = __shfl_down_sync(0xffffffffu, bj, o);
                if (v2 > bv || (v2 == bv && i2 < bj)) { bv = v2; bj = i2; }
            }
            if (lane == 0) { s_wval[wid] = bv; s_widx[wid] = bj; }
        }
        __syncthreads();
    }

    unsigned mask = 0;
    for (int t = 0; t < radius; t++) {
        int j = s_idx[t];
        if (((j & 1023) >> 2) == tid) mask |= 1u << ((j >> 10) * 4 + (j & 3));
    }

    // ---- quad = 0.5 * d^T W d ----
    float q = 0.f;
    int rr = radius * radius;
    for (int p = tid; p < rr; p += ST) {
        int a = p / radius, bb = p - a * radius;
        int ia = s_idx[a], ib = s_idx[bb];
        float da = 1.f - 2.f * xr[ia];
        float db = 1.f - 2.f * xr[ib];
        q += da * db * W[(size_t)ia * DD + ib];
    }
    #pragma unroll
    for (int o = 16; o > 0; o >>= 1) q += __shfl_xor_sync(0xffffffffu, q, o);
    __syncthreads();
    if (lane == 0) s_red[wid] = q;
    __syncthreads();
    float quad = 0.f;
    #pragma unroll
    for (int ww = 0; ww < NW; ww++) quad += s_red[ww];
    quad *= 0.5f;
    __syncthreads();

    // ---- lse_y ----
    float m2 = -FLT_MAX;
    #pragma unroll
    for (int k = 0; k < 16; k++) {
        float v = (mask >> k) & 1 ? -scx[k] : scx[k];
        m2 = fmaxf(m2, v);
    }
    #pragma unroll
    for (int o = 16; o > 0; o >>= 1) m2 = fmaxf(m2, __shfl_xor_sync(0xffffffffu, m2, o));
    if (lane == 0) s_red[wid] = m2;
    __syncthreads();
    float mx2 = s_red[0];
    #pragma unroll
    for (int ww = 1; ww < NW; ww++) mx2 = fmaxf(mx2, s_red[ww]);
    __syncthreads();
    float s2 = 0.f;
    #pragma unroll
    for (int k = 0; k < 16; k++) {
        float v = (mask >> k) & 1 ? -scx[k] : scx[k];
        s2 += __expf(v - mx2);
    }
    #pragma unroll
    for (int o = 16; o > 0; o >>= 1) s2 += __shfl_xor_sync(0xffffffffu, s2, o);
    if (lane == 0) s_red[wid] = s2;
    __syncthreads();
    float ss2 = 0.f;
    #pragma unroll
    for (int ww = 0; ww < NW; ww++) ss2 += s_red[ww];
    float lse_y = mx2 + logf(ss2);

    // ---- accept + write ----
    float la = fminf(quad + lse_x - lse_y, 0.f);
    int accept = (__expf(la) > u[row]) ? 1 : 0;

    float* outr = out + (size_t)row * DD;
    #pragma unroll
    for (int g = 0; g < 4; g++) {
        int base = g * 1024 + tid * 4;
        float4 o4;
        float* po = (float*)&o4;
        #pragma unroll
        for (int e = 0; e < 4; e++) {
            int k = g * 4 + e;
            float yv = ((mask >> k) & 1) ? (1.f - xv[k]) : xv[k];
            po[e] = accept ? yv : xv[k];
        }
        *(float4*)&outr[base] = o4;
    }
}

// ---------------------------------------------------------------------------
extern "C" void kernel_launch(void* const* d_in, const int* in_sizes, int n_in,
                              void* d_out, int out_size) {
    const float* x          = (const float*)d_in[0];
    const float* W          = (const float*)d_in[1];
    const float* bias       = (const float*)d_in[2];
    const int*   radius_raw = (const int*)d_in[3];
    const float* gum        = (const float*)d_in[4];
    const float* u          = (const float*)d_in[5];
    float* out = (float*)d_out;

    cudaFuncSetAttribute(k_gemm_f, cudaFuncAttributeMaxDynamicSharedMemorySize, GSMEM);

    k_convX<<<(BD * DD) / 1024, 256>>>(x);
    k_gemm_f<<<dim3(DD / TN, BD / TM), 256, GSMEM>>>(W, bias);
    k_sample<<<BD, ST>>>(x, W, radius_raw, gum, u, out);
}

// round 13
// speedup vs baseline: 2.5736x; 2.4616x over previous
#include <cuda_runtime.h>
#include <cuda_bf16.h>
#include <math.h>
#include <float.h>
#include <stdint.h>

#define BD 256      // batch
#define DD 4096     // dim

// Scratch (allocation-free: device globals)
__device__ __nv_bfloat16 g_Mhi[(size_t)DD * DD];   // bf16 hi of W + W^T (symmetric)
__device__ __nv_bfloat16 g_Mlo[(size_t)DD * DD];   // bf16 residual (symmetric)
__device__ __nv_bfloat16 g_Xbf[(size_t)BD * DD];   // x in bf16 (exact: binary)
__device__ float         g_grad[(size_t)BD * DD];  // grad = 0.5(W+W^T)x + b

// ===========================================================================
// helpers
// ===========================================================================
__device__ __forceinline__ uint32_t smem_u32(const void* p) {
    uint32_t a;
    asm("{ .reg .u64 t; cvta.to.shared.u64 t, %1; cvt.u32.u64 %0, t; }" : "=r"(a) : "l"(p));
    return a;
}
__device__ __forceinline__ void cp16(uint32_t s, const void* g) {
    asm volatile("cp.async.cg.shared.global [%0], [%1], 16;\n" :: "r"(s), "l"(g));
}
#define CP_COMMIT() asm volatile("cp.async.commit_group;\n" ::: "memory")
#define CP_WAIT2()  asm volatile("cp.async.wait_group 2;\n" ::: "memory")

__device__ __forceinline__ void ldmx4(uint32_t* r, uint32_t a) {
    asm volatile("ldmatrix.sync.aligned.m8n8.x4.shared.b16 {%0,%1,%2,%3}, [%4];\n"
                 : "=r"(r[0]), "=r"(r[1]), "=r"(r[2]), "=r"(r[3]) : "r"(a));
}
__device__ __forceinline__ void ldmx4t(uint32_t* r, uint32_t a) {
    asm volatile("ldmatrix.sync.aligned.m8n8.x4.trans.shared.b16 {%0,%1,%2,%3}, [%4];\n"
                 : "=r"(r[0]), "=r"(r[1]), "=r"(r[2]), "=r"(r[3]) : "r"(a));
}
__device__ __forceinline__ void mma16816(float* d, const uint32_t* a, uint32_t b0, uint32_t b1) {
    asm volatile(
        "mma.sync.aligned.m16n8k16.row.col.f32.bf16.bf16.f32 "
        "{%0,%1,%2,%3}, {%4,%5,%6,%7}, {%8,%9}, {%0,%1,%2,%3};\n"
        : "+f"(d[0]), "+f"(d[1]), "+f"(d[2]), "+f"(d[3])
        : "r"(a[0]), "r"(a[1]), "r"(a[2]), "r"(a[3]), "r"(b0), "r"(b1));
}
__device__ __forceinline__ uint32_t swz(uint32_t off) {   // SW128
    return off ^ ((off >> 3) & 0x70);
}

// ---------------------------------------------------------------------------
// Kernel 1: M = W + W^T -> bf16 hi + bf16 lo. 64x64 tile pairs (by <= bx).
// Idle CTAs (by > bx): first 1024 of them do the x -> bf16 conversion.
// ---------------------------------------------------------------------------
__global__ __launch_bounds__(256) void k_buildM(const float* __restrict__ W,
                                                const float* __restrict__ x) {
    int bx = blockIdx.x, by = blockIdx.y;
    int tid = threadIdx.x;

    if (by > bx) {
        // triangular index 0..2015; first 1024 blocks convert x (1 float4/thread)
        int idx = (by * (by - 1)) / 2 + bx;
        if (idx < (BD * DD) / 4 / 256) {
            int i = (idx * 256 + tid) * 4;
            float4 v = *(const float4*)&x[i];
            __nv_bfloat162 p0; p0.x = __float2bfloat16(v.x); p0.y = __float2bfloat16(v.y);
            __nv_bfloat162 p1; p1.x = __float2bfloat16(v.z); p1.y = __float2bfloat16(v.w);
            *(__nv_bfloat162*)&g_Xbf[i]     = p0;
            *(__nv_bfloat162*)&g_Xbf[i + 2] = p1;
        }
        return;
    }

    __shared__ float t1[64][65];
    __shared__ float t2[64][65];
    int r1 = by * 64, c1 = bx * 64;
    bool diag = (bx == by);

    #pragma unroll
    for (int i = 0; i < 4; i++) {
        int chunk = tid + i * 256;
        int row = chunk >> 4;
        int c4  = (chunk & 15) * 4;
        float4 v1 = *(const float4*)&W[(size_t)(r1 + row) * DD + c1 + c4];
        t1[row][c4] = v1.x; t1[row][c4+1] = v1.y; t1[row][c4+2] = v1.z; t1[row][c4+3] = v1.w;
        if (!diag) {
            float4 v2 = *(const float4*)&W[(size_t)(c1 + row) * DD + r1 + c4];
            t2[row][c4] = v2.x; t2[row][c4+1] = v2.y; t2[row][c4+2] = v2.z; t2[row][c4+3] = v2.w;
        } else {
            t2[row][c4] = v1.x; t2[row][c4+1] = v1.y; t2[row][c4+2] = v1.z; t2[row][c4+3] = v1.w;
        }
    }
    __syncthreads();

    #pragma unroll
    for (int i = 0; i < 2; i++) {
        int u   = tid + i * 256;
        int row = u >> 3;
        int cg  = (u & 7) * 8;
        {
            __align__(16) __nv_bfloat16 hi[8], lo[8];
            #pragma unroll
            for (int e = 0; e < 8; e++) {
                float a = t1[row][cg + e] + t2[cg + e][row];
                __nv_bfloat16 h = __float2bfloat16(a);
                hi[e] = h;
                lo[e] = __float2bfloat16(a - __bfloat162float(h));
            }
            size_t off = (size_t)(r1 + row) * DD + c1 + cg;
            *(uint4*)&g_Mhi[off] = *(uint4*)hi;
            *(uint4*)&g_Mlo[off] = *(uint4*)lo;
        }
        if (!diag) {
            __align__(16) __nv_bfloat16 hi[8], lo[8];
            #pragma unroll
            for (int e = 0; e < 8; e++) {
                float a = t2[row][cg + e] + t1[cg + e][row];
                __nv_bfloat16 h = __float2bfloat16(a);
                hi[e] = h;
                lo[e] = __float2bfloat16(a - __bfloat162float(h));
            }
            size_t off = (size_t)(c1 + row) * DD + r1 + cg;
            *(uint4*)&g_Mhi[off] = *(uint4*)hi;
            *(uint4*)&g_Mlo[off] = *(uint4*)lo;
        }
    }
}

// ---------------------------------------------------------------------------
// Kernel 2: GEMM  grad = 0.5 * (Xbf @ Mhi + Xbf @ Mlo) + bias
// R7 skeleton (BM=BN=BK=64, 128 thr, 4-stage dist-3, SW128) with SPLIT
// accumulators: acc_h for hi-MMAs, acc_l for lo-MMAs (16 independent chains).
// ---------------------------------------------------------------------------
#define TM 64
#define TN 64
#define TKK 64
#define GNIT (DD / TKK)          // 64
#define GTILE 8192               // 64 rows x 128B
#define GSTAGE_B (3 * GTILE)     // 24KB
#define GSMEM (4 * GSTAGE_B + 1024)

extern __shared__ char g_dynsm[];

__global__ __launch_bounds__(128) void k_gemm(const float* __restrict__ bias) {
    int tid  = threadIdx.x;
    int lane = tid & 31, w = tid >> 5;
    int m0 = blockIdx.y * TM;
    int n0 = blockIdx.x * TN;
    int wm = (w >> 1) * 32;
    int wn = (w & 1) * 32;

    uint32_t base = (smem_u32(g_dynsm) + 1023u) & ~1023u;

    float acc_h[2][4][4], acc_l[2][4][4];
    #pragma unroll
    for (int a = 0; a < 2; a++)
        #pragma unroll
        for (int b = 0; b < 4; b++)
            #pragma unroll
            for (int c = 0; c < 4; c++) { acc_h[a][b][c] = 0.f; acc_l[a][b][c] = 0.f; }

    const __nv_bfloat16* gA = g_Xbf + (size_t)m0 * DD;
    const __nv_bfloat16* gH = g_Mhi + (size_t)n0;
    const __nv_bfloat16* gL = g_Mlo + (size_t)n0;

    auto load_stage = [&](int s, int it) {
        int k0 = it * TKK;
        uint32_t sb = base + s * GSTAGE_B;
        #pragma unroll
        for (int i = 0; i < 4; i++) {
            int id  = tid + i * 128;
            int row = id >> 3;
            int ce  = (id & 7) * 8;
            uint32_t d = swz((uint32_t)(row * 128 + ce * 2));
            cp16(sb + d,              gA + (size_t)row * DD + k0 + ce);
            cp16(sb + GTILE + d,      gH + (size_t)(k0 + row) * DD + ce);
            cp16(sb + 2 * GTILE + d,  gL + (size_t)(k0 + row) * DD + ce);
        }
    };

    #pragma unroll
    for (int s = 0; s < 3; s++) { load_stage(s, s); CP_COMMIT(); }

    int lm = lane & 15, lh = (lane >> 4) * 8;

    for (int it = 0; it < GNIT; it++) {
        int s = it & 3;
        CP_WAIT2();
        __syncthreads();
        if (it + 3 < GNIT) load_stage((it + 3) & 3, it + 3);
        CP_COMMIT();

        uint32_t sbA = base + s * GSTAGE_B;
        uint32_t sbH = sbA + GTILE;
        uint32_t sbL = sbA + 2 * GTILE;

        #pragma unroll
        for (int ks = 0; ks < TKK; ks += 16) {
            uint32_t af[2][4], bh[2][4], bl[2][4];
            #pragma unroll
            for (int mt = 0; mt < 2; mt++) {
                uint32_t byte = (uint32_t)((wm + mt * 16 + lm) * 128 + (ks + lh) * 2);
                ldmx4(af[mt], sbA + swz(byte));
            }
            #pragma unroll
            for (int nb = 0; nb < 2; nb++) {
                uint32_t byte = (uint32_t)((ks + lm) * 128 + (wn + nb * 16 + lh) * 2);
                ldmx4t(bh[nb], sbH + swz(byte));
                ldmx4t(bl[nb], sbL + swz(byte));
            }
            #pragma unroll
            for (int nt = 0; nt < 4; nt++) {
                int nb = nt >> 1, sel = (nt & 1) * 2;
                #pragma unroll
                for (int mt = 0; mt < 2; mt++) {
                    mma16816(acc_h[mt][nt], af[mt], bh[nb][sel], bh[nb][sel + 1]);
                    mma16816(acc_l[mt][nt], af[mt], bl[nb][sel], bl[nb][sel + 1]);
                }
            }
        }
    }

    int r = lane >> 2, c2 = (lane & 3) * 2;
    #pragma unroll
    for (int mt = 0; mt < 2; mt++)
        #pragma unroll
        for (int nt = 0; nt < 4; nt++) {
            int grow = m0 + wm + mt * 16 + r;
            int gcol = n0 + wn + nt * 8 + c2;
            float b0v = bias[gcol], b1v = bias[gcol + 1];
            g_grad[(size_t)grow * DD + gcol] =
                0.5f * (acc_h[mt][nt][0] + acc_l[mt][nt][0]) + b0v;
            g_grad[(size_t)grow * DD + gcol + 1] =
                0.5f * (acc_h[mt][nt][1] + acc_l[mt][nt][1]) + b1v;
            g_grad[(size_t)(grow + 8) * DD + gcol] =
                0.5f * (acc_h[mt][nt][2] + acc_l[mt][nt][2]) + b0v;
            g_grad[(size_t)(grow + 8) * DD + gcol + 1] =
                0.5f * (acc_h[mt][nt][3] + acc_l[mt][nt][3]) + b1v;
        }
}

// ---------------------------------------------------------------------------
// Kernel 3: per-row sampler (R7, verified ~18us)
// ---------------------------------------------------------------------------
#define ST 256
#define NW (ST / 32)

__global__ __launch_bounds__(ST) void k_sample(
    const float* __restrict__ x, const float* __restrict__ W,
    const int* __restrict__ radius_raw, const float* __restrict__ gum,
    const float* __restrict__ u, float* __restrict__ out)
{
    int row = blockIdx.x;
    int tid = threadIdx.x;
    int lane = tid & 31, wid = tid >> 5;

    __shared__ float s_wval[NW];
    __shared__ int   s_widx[NW];
    __shared__ float s_red[NW];
    __shared__ int   s_win;
    __shared__ int   s_idx[16];

    const float* xr  = x      + (size_t)row * DD;
    const float* gr  = g_grad + (size_t)row * DD;
    const float* gur = gum    + (size_t)row * DD;

    float4 vx[4], vg[4], vu[4];
    #pragma unroll
    for (int g = 0; g < 4; g++) vx[g] = *(const float4*)&xr[g * 1024 + tid * 4];
    #pragma unroll
    for (int g = 0; g < 4; g++) vg[g] = *(const float4*)&gr[g * 1024 + tid * 4];
    #pragma unroll
    for (int g = 0; g < 4; g++) vu[g] = *(const float4*)&gur[g * 1024 + tid * 4];

    float xv[16], scx[16], key[16];
    #pragma unroll
    for (int g = 0; g < 4; g++) {
        float fx[4] = {vx[g].x, vx[g].y, vx[g].z, vx[g].w};
        float fg[4] = {vg[g].x, vg[g].y, vg[g].z, vg[g].w};
        float fu[4] = {vu[g].x, vu[g].y, vu[g].z, vu[g].w};
        #pragma unroll
        for (int e = 0; e < 4; e++) {
            int k = g * 4 + e;
            xv[k]  = fx[e];
            scx[k] = (0.5f - fx[e]) * fg[e];
            float uu = fminf(fmaxf(fu[e], 1e-10f), 1.0f - 1e-10f);
            key[k] = scx[k] - __logf(-__logf(uu));
        }
    }

    // ---- lse_x ----
    float m = -FLT_MAX;
    #pragma unroll
    for (int k = 0; k < 16; k++) m = fmaxf(m, scx[k]);
    #pragma unroll
    for (int o = 16; o > 0; o >>= 1) m = fmaxf(m, __shfl_xor_sync(0xffffffffu, m, o));
    if (lane == 0) s_red[wid] = m;
    __syncthreads();
    float mx = s_red[0];
    #pragma unroll
    for (int ww = 1; ww < NW; ww++) mx = fmaxf(mx, s_red[ww]);
    __syncthreads();
    float s = 0.f;
    #pragma unroll
    for (int k = 0; k < 16; k++) s += __expf(scx[k] - mx);
    #pragma unroll
    for (int o = 16; o > 0; o >>= 1) s += __shfl_xor_sync(0xffffffffu, s, o);
    if (lane == 0) s_red[wid] = s;
    __syncthreads();
    float ss = 0.f;
    #pragma unroll
    for (int ww = 0; ww < NW; ww++) ss += s_red[ww];
    float lse_x = mx + logf(ss);

    // ---- initial per-warp candidate ----
    {
        float bv = -FLT_MAX; int bk = 0;
        #pragma unroll
        for (int k = 0; k < 16; k++)
            if (key[k] > bv) { bv = key[k]; bk = k; }
        int bj = (bk >> 2) * 1024 + tid * 4 + (bk & 3);
        #pragma unroll
        for (int o = 16; o > 0; o >>= 1) {
            float v2 = __shfl_down_sync(0xffffffffu, bv, o);
            int   i2 = __shfl_down_sync(0xffffffffu, bj, o);
            if (v2 > bv || (v2 == bv && i2 < bj)) { bv = v2; bj = i2; }
        }
        if (lane == 0) { s_wval[wid] = bv; s_widx[wid] = bj; }
    }
    __syncthreads();

    // ---- top-radius: winner-warp-only rescan ----
    int radius = radius_raw[row] + 1;
    for (int t = 0; t < radius; t++) {
        if (tid == 0) {
            float wv = s_wval[0]; int wj = s_widx[0]; int wwin = 0;
            #pragma unroll
            for (int ww = 1; ww < NW; ww++) {
                float v2 = s_wval[ww]; int i2 = s_widx[ww];
                if (v2 > wv || (v2 == wv && i2 < wj)) { wv = v2; wj = i2; wwin = ww; }
            }
            s_idx[t] = wj; s_win = wwin;
        }
        __syncthreads();
        if (wid == s_win && t + 1 < radius) {
            int j = s_idx[t];
            if (((j & 1023) >> 2) == tid) key[(j >> 10) * 4 + (j & 3)] = -FLT_MAX;
            float bv = -FLT_MAX; int bk = 0;
            #pragma unroll
            for (int k = 0; k < 16; k++)
                if (key[k] > bv) { bv = key[k]; bk = k; }
            int bj = (bk >> 2) * 1024 + tid * 4 + (bk & 3);
            #pragma unroll
            for (int o = 16; o > 0; o >>= 1) {
                float v2 = __shfl_down_sync(0xffffffffu, bv, o);
                int   i2 = __shfl_down_sync(0xffffffffu, bj, o);
                if (v2 > bv || (v2 == bv && i2 < bj)) { bv = v2; bj = i2; }
            }
            if (lane == 0) { s_wval[wid] = bv; s_widx[wid] = bj; }
        }
        __syncthreads();
    }

    unsigned mask = 0;
    for (int t = 0; t < radius; t++) {
        int j = s_idx[t];
        if (((j & 1023) >> 2) == tid) mask |= 1u << ((j >> 10) * 4 + (j & 3));
    }

    // ---- quad = 0.5 * d^T W d ----
    float q = 0.f;
    int rr = radius * radius;
    for (int p = tid; p < rr; p += ST) {
        int a = p / radius, bb = p - a * radius;
        int ia = s_idx[a], ib = s_idx[bb];
        float da = 1.f - 2.f * xr[ia];
        float db = 1.f - 2.f * xr[ib];
        q += da * db * W[(size_t)ia * DD + ib];
    }
    #pragma unroll
    for (int o = 16; o > 0; o >>= 1) q += __shfl_xor_sync(0xffffffffu, q, o);
    __syncthreads();
    if (lane == 0) s_red[wid] = q;
    __syncthreads();
    float quad = 0.f;
    #pragma unroll
    for (int ww = 0; ww < NW; ww++) quad += s_red[ww];
    quad *= 0.5f;
    __syncthreads();

    // ---- lse_y ----
    float m2 = -FLT_MAX;
    #pragma unroll
    for (int k = 0; k < 16; k++) {
        float v = (mask >> k) & 1 ? -scx[k] : scx[k];
        m2 = fmaxf(m2, v);
    }
    #pragma unroll
    for (int o = 16; o > 0; o >>= 1) m2 = fmaxf(m2, __shfl_xor_sync(0xffffffffu, m2, o));
    if (lane == 0) s_red[wid] = m2;
    __syncthreads();
    float mx2 = s_red[0];
    #pragma unroll
    for (int ww = 1; ww < NW; ww++) mx2 = fmaxf(mx2, s_red[ww]);
    __syncthreads();
    float s2 = 0.f;
    #pragma unroll
    for (int k = 0; k < 16; k++) {
        float v = (mask >> k) & 1 ? -scx[k] : scx[k];
        s2 += __expf(v - mx2);
    }
    #pragma unroll
    for (int o = 16; o > 0; o >>= 1) s2 += __shfl_xor_sync(0xffffffffu, s2, o);
    if (lane == 0) s_red[wid] = s2;
    __syncthreads();
    float ss2 = 0.f;
    #pragma unroll
    for (int ww = 0; ww < NW; ww++) ss2 += s_red[ww];
    float lse_y = mx2 + logf(ss2);

    // ---- accept + write ----
    float la = fminf(quad + lse_x - lse_y, 0.f);
    int accept = (__expf(la) > u[row]) ? 1 : 0;

    float* outr = out + (size_t)row * DD;
    #pragma unroll
    for (int g = 0; g < 4; g++) {
        int base = g * 1024 + tid * 4;
        float4 o4;
        float* po = (float*)&o4;
        #pragma unroll
        for (int e = 0; e < 4; e++) {
            int k = g * 4 + e;
            float yv = ((mask >> k) & 1) ? (1.f - xv[k]) : xv[k];
            po[e] = accept ? yv : xv[k];
        }
        *(float4*)&outr[base] = o4;
    }
}

// ---------------------------------------------------------------------------
extern "C" void kernel_launch(void* const* d_in, const int* in_sizes, int n_in,
                              void* d_out, int out_size) {
    const float* x          = (const float*)d_in[0];
    const float* W          = (const float*)d_in[1];
    const float* bias       = (const float*)d_in[2];
    const int*   radius_raw = (const int*)d_in[3];
    const float* gum        = (const float*)d_in[4];
    const float* u          = (const float*)d_in[5];
    float* out = (float*)d_out;

    cudaFuncSetAttribute(k_gemm, cudaFuncAttributeMaxDynamicSharedMemorySize, GSMEM);

    k_buildM<<<dim3(DD / 64, DD / 64), 256>>>(W, x);
    k_gemm<<<dim3(DD / TN, BD / TM), 128, GSMEM>>>(bias);
    k_sample<<<BD, ST>>>(x, W, radius_raw, gum, u, out);
}